// round 13
// baseline (speedup 1.0000x reference)
#include <cuda_runtime.h>
#include <math.h>

#define N_NODES 50000
#define E_EDGES 640000
#define NG 50
#define NGRAPHS 64

typedef unsigned int u32;

// ---------------- scratch ----------------------------------------------------
__device__ __align__(16) float g_d[E_EDGES];
__device__ __align__(16) float g_C[E_EDGES];
__device__ __align__(16) int   g_src[E_EDGES];
__device__ __align__(16) int   g_dst[E_EDGES];
__device__ __align__(16) float g_h[(size_t)N_NODES * 128];
__device__ __align__(16) float g_xf[(size_t)N_NODES * 128];
__device__ __align__(16) float g_agg[(size_t)N_NODES * 128];
__device__ int g_is64;

// pre-packed bf16x2 weights: layout [n][k-pair]
__device__ __align__(16) u32 pk_c1[3 * 128 * 64];
__device__ __align__(16) u32 pk_c2[3 * 128 * 64];
__device__ __align__(16) u32 pk_l [3 * 128 * 64];
__device__ __align__(16) u32 pk_w1[3 * 128 * 32];
__device__ __align__(16) u32 pk_w2[3 * 128 * 64];

// ---------------- helpers -----------------------------------------------------
__device__ __forceinline__ u32 pack_bf(float lo, float hi) {
    u32 r; asm("cvt.rn.bf16x2.f32 %0,%1,%2;" : "=r"(r) : "f"(hi), "f"(lo)); return r;
}
__device__ __forceinline__ void mma16(float& c0, float& c1, float& c2, float& c3,
                                      u32 a0, u32 a1, u32 a2, u32 a3, u32 b0, u32 b1) {
    asm("mma.sync.aligned.m16n8k16.row.col.f32.bf16.bf16.f32 "
        "{%0,%1,%2,%3},{%4,%5,%6,%7},{%8,%9},{%0,%1,%2,%3};"
        : "+f"(c0), "+f"(c1), "+f"(c2), "+f"(c3)
        : "r"(a0), "r"(a1), "r"(a2), "r"(a3), "r"(b0), "r"(b1));
}
__device__ __forceinline__ float ex2f(float x) { float r; asm("ex2.approx.ftz.f32 %0,%1;" : "=f"(r) : "f"(x)); return r; }
__device__ __forceinline__ float lg2f_(float x) { float r; asm("lg2.approx.ftz.f32 %0,%1;" : "=f"(r) : "f"(x)); return r; }
__device__ __forceinline__ float ssp_fast(float x) {
    float e = ex2f(x * 1.4426950408889634f);
    return 0.6931471805599453f * (lg2f_(1.0f + e) - 1.0f);
}
__device__ __forceinline__ float sspf(float x) {
    float ax = fabsf(x);
    float sp = log1pf(__expf(-ax));
    return (x > 0.f ? x + sp : sp) - 0.6931471805599453f;
}
__device__ __forceinline__ void red2(float* p, float v0, float v1) {
    asm volatile("red.global.add.v2.f32 [%0], {%1,%2};" :: "l"(p), "f"(v0), "f"(v1) : "memory");
}

// ---------------- small kernels ----------------------------------------------
__global__ void detect_kernel(const int* __restrict__ ei) {
    if (threadIdx.x == 0 && blockIdx.x == 0) {
        int acc = ei[1] | ei[3] | ei[5] | ei[7] | ei[9] | ei[11] | ei[13] | ei[15];
        g_is64 = (acc == 0) ? 1 : 0;
    }
}
__global__ void prep_kernel(const int* __restrict__ ei, const float* __restrict__ pos) {
    int e = blockIdx.x * blockDim.x + threadIdx.x;
    if (e >= E_EDGES) return;
    int s, t;
    if (g_is64) { const long long* q = (const long long*)ei; s = (int)q[e]; t = (int)q[E_EDGES + e]; }
    else { s = ei[e]; t = ei[E_EDGES + e]; }
    float dx = pos[t * 3 + 0] - pos[s * 3 + 0];
    float dy = pos[t * 3 + 1] - pos[s * 3 + 1];
    float dz = pos[t * 3 + 2] - pos[s * 3 + 2];
    float d = sqrtf(dx * dx + dy * dy + dz * dz);
    g_src[e] = s; g_dst[e] = t; g_d[e] = d;
    g_C[e] = 0.5f * (cosf(d * 0.62831853071795864f) + 1.0f);
}
__global__ void embed_kernel(const int* __restrict__ z, const float* __restrict__ emb) {
    int i = blockIdx.x * blockDim.x + threadIdx.x;
    if (i >= N_NODES * 32) return;
    int n = i >> 5, c4 = (i & 31) * 4;
    *(float4*)&g_h[(size_t)n * 128 + c4] = *(const float4*)&emb[z[n] * 128 + c4];
}

// ---------------- weight pre-pack ---------------------------------------------
__global__ void pack_kernel(const float* __restrict__ c1, const float* __restrict__ c2,
                            const float* __restrict__ lw, const float* __restrict__ w1,
                            const float* __restrict__ w2) {
    int i = blockIdx.x * blockDim.x + threadIdx.x;
    if (i < 3 * 128 * 64) {
        int l = i >> 13, n = (i >> 6) & 127, wd = i & 63;
        int base = l * 16384, k0 = 2 * wd;
        pk_c1[i] = pack_bf(c1[base + k0 * 128 + n], c1[base + (k0 + 1) * 128 + n]);
        pk_c2[i] = pack_bf(c2[base + k0 * 128 + n], c2[base + (k0 + 1) * 128 + n]);
        pk_l[i]  = pack_bf(lw[base + k0 * 128 + n], lw[base + (k0 + 1) * 128 + n]);
        pk_w2[i] = pack_bf(w2[base + k0 * 128 + n], w2[base + (k0 + 1) * 128 + n]);
    }
    if (i < 3 * 128 * 32) {
        int l = i >> 12, n = (i >> 5) & 127, wd = i & 31;
        int base = l * NG * 128, k0 = 2 * wd;
        float v0 = (k0 < NG) ? w1[base + k0 * 128 + n] : 0.f;
        float v1 = (k0 + 1 < NG) ? w1[base + (k0 + 1) * 128 + n] : 0.f;
        pk_w1[l * 4096 + n * 32 + wd] = pack_bf(v0, v1);
    }
}

#define W1S 36
#define W2S 68

// ---------------- conv1 (layer 0 only) ----------------------------------------
__global__ __launch_bounds__(256, 3) void mm_conv1(const float* __restrict__ A,
                                                   const u32* __restrict__ pkW,
                                                   float* __restrict__ Cout) {
    extern __shared__ u32 sm[];
    u32* As = sm;
    u32* Ws = sm + 64 * W2S;
    int tid = threadIdx.x, lane = tid & 31, w = tid >> 5;
    int row0 = blockIdx.x * 64;

    for (int i = tid; i < 64 * 64; i += 256) {
        int r = i >> 6, wd = i & 63;
        int row = row0 + r;
        float2 v = make_float2(0.f, 0.f);
        if (row < N_NODES) v = *(const float2*)(A + (size_t)row * 128 + 2 * wd);
        As[r * W2S + wd] = pack_bf(v.x, v.y);
    }
    for (int i = tid; i < 128 * 64; i += 256)
        Ws[(i >> 6) * W2S + (i & 63)] = pkW[i];
    __syncthreads();

    int g = lane >> 2, t4 = lane & 3;
    int n0 = w * 16;
    float c[4][2][4];
    #pragma unroll
    for (int m = 0; m < 4; m++)
        #pragma unroll
        for (int n = 0; n < 2; n++)
            #pragma unroll
            for (int q = 0; q < 4; q++) c[m][n][q] = 0.f;

    #pragma unroll
    for (int kk = 0; kk < 8; kk++) {
        int wb = kk * 8 + t4;
        u32 b[2][2];
        #pragma unroll
        for (int n = 0; n < 2; n++) {
            int col = n0 + n * 8 + g;
            b[n][0] = Ws[col * W2S + wb];
            b[n][1] = Ws[col * W2S + wb + 4];
        }
        #pragma unroll
        for (int m = 0; m < 4; m++) {
            int r = m * 16 + g;
            u32 a0 = As[r * W2S + wb],     a1 = As[(r + 8) * W2S + wb];
            u32 a2 = As[r * W2S + wb + 4], a3 = As[(r + 8) * W2S + wb + 4];
            #pragma unroll
            for (int n = 0; n < 2; n++)
                mma16(c[m][n][0], c[m][n][1], c[m][n][2], c[m][n][3], a0, a1, a2, a3, b[n][0], b[n][1]);
        }
    }
    #pragma unroll
    for (int m = 0; m < 4; m++)
        #pragma unroll
        for (int n = 0; n < 2; n++) {
            int col = n0 + n * 8 + 2 * t4;
            #pragma unroll
            for (int h = 0; h < 2; h++) {
                int row = row0 + m * 16 + g + h * 8;
                if (row < N_NODES)
                    *(float2*)(Cout + (size_t)row * 128 + col) =
                        make_float2(c[m][n][2 * h], c[m][n][2 * h + 1]);
            }
        }
}

// ---------------- fused conv2 + lin (+ next conv1); zeroes agg ---------------
__global__ __launch_bounds__(256, 3) void gemm2f(float* __restrict__ Agg,
                                                 const u32* __restrict__ pkW2,
                                                 const float* __restrict__ b2,
                                                 const u32* __restrict__ pkW3,
                                                 const float* __restrict__ b3,
                                                 const u32* __restrict__ pkWc1,
                                                 float* __restrict__ H,
                                                 float* __restrict__ Xf,
                                                 int has_c1) {
    extern __shared__ u32 sm[];
    u32* As = sm;
    u32* Ws = sm + 64 * W2S;
    float* b2s = (float*)(Ws + 128 * W2S);
    float* b3s = b2s + 128;
    int tid = threadIdx.x, lane = tid & 31, w = tid >> 5;
    int row0 = blockIdx.x * 64;
    int g = lane >> 2, t4 = lane & 3;
    int n0 = w * 16;

    for (int i = tid; i < 64 * 64; i += 256) {
        int r = i >> 6, wd = i & 63;
        int row = row0 + r;
        float2 v = make_float2(0.f, 0.f);
        if (row < N_NODES) {
            float* p = Agg + (size_t)row * 128 + 2 * wd;
            v = *(float2*)p;
            *(float2*)p = make_float2(0.f, 0.f);
        }
        As[r * W2S + wd] = pack_bf(v.x, v.y);
    }
    for (int i = tid; i < 128 * 64; i += 256)
        Ws[(i >> 6) * W2S + (i & 63)] = pkW2[i];
    if (tid < 128) { b2s[tid] = b2[tid]; b3s[tid] = b3[tid]; }
    __syncthreads();

    float c[4][2][4];
    #pragma unroll
    for (int m = 0; m < 4; m++)
        #pragma unroll
        for (int n = 0; n < 2; n++)
            #pragma unroll
            for (int q = 0; q < 4; q++) c[m][n][q] = 0.f;

    // ---- phase A: agg @ W2 ----
    #pragma unroll
    for (int kk = 0; kk < 8; kk++) {
        int wb = kk * 8 + t4;
        u32 b[2][2];
        #pragma unroll
        for (int n = 0; n < 2; n++) {
            int col = n0 + n * 8 + g;
            b[n][0] = Ws[col * W2S + wb];
            b[n][1] = Ws[col * W2S + wb + 4];
        }
        #pragma unroll
        for (int m = 0; m < 4; m++) {
            int r = m * 16 + g;
            u32 a0 = As[r * W2S + wb],     a1 = As[(r + 8) * W2S + wb];
            u32 a2 = As[r * W2S + wb + 4], a3 = As[(r + 8) * W2S + wb + 4];
            #pragma unroll
            for (int n = 0; n < 2; n++)
                mma16(c[m][n][0], c[m][n][1], c[m][n][2], c[m][n][3], a0, a1, a2, a3, b[n][0], b[n][1]);
        }
    }
    __syncthreads();

    // t = ssp(c + b2) -> As ; Ws <- W3
    #pragma unroll
    for (int m = 0; m < 4; m++)
        #pragma unroll
        for (int n = 0; n < 2; n++) {
            int col = n0 + n * 8 + 2 * t4;
            int wd = w * 8 + n * 4 + t4;
            #pragma unroll
            for (int h = 0; h < 2; h++) {
                int row = m * 16 + g + h * 8;
                As[row * W2S + wd] = pack_bf(ssp_fast(c[m][n][2 * h] + b2s[col]),
                                             ssp_fast(c[m][n][2 * h + 1] + b2s[col + 1]));
            }
        }
    for (int i = tid; i < 128 * 64; i += 256)
        Ws[(i >> 6) * W2S + (i & 63)] = pkW3[i];
    __syncthreads();

    // ---- phase B: t @ W3 ----
    #pragma unroll
    for (int m = 0; m < 4; m++)
        #pragma unroll
        for (int n = 0; n < 2; n++)
            #pragma unroll
            for (int q = 0; q < 4; q++) c[m][n][q] = 0.f;
    #pragma unroll
    for (int kk = 0; kk < 8; kk++) {
        int wb = kk * 8 + t4;
        u32 b[2][2];
        #pragma unroll
        for (int n = 0; n < 2; n++) {
            int col = n0 + n * 8 + g;
            b[n][0] = Ws[col * W2S + wb];
            b[n][1] = Ws[col * W2S + wb + 4];
        }
        #pragma unroll
        for (int m = 0; m < 4; m++) {
            int r = m * 16 + g;
            u32 a0 = As[r * W2S + wb],     a1 = As[(r + 8) * W2S + wb];
            u32 a2 = As[r * W2S + wb + 4], a3 = As[(r + 8) * W2S + wb + 4];
            #pragma unroll
            for (int n = 0; n < 2; n++)
                mma16(c[m][n][0], c[m][n][1], c[m][n][2], c[m][n][3], a0, a1, a2, a3, b[n][0], b[n][1]);
        }
    }
    __syncthreads();

    // hnew = h + c + b3 -> H (and As for phase C) ; Ws <- Wc1
    #pragma unroll
    for (int m = 0; m < 4; m++)
        #pragma unroll
        for (int n = 0; n < 2; n++) {
            int col = n0 + n * 8 + 2 * t4;
            int wd = w * 8 + n * 4 + t4;
            #pragma unroll
            for (int h = 0; h < 2; h++) {
                int lrow = m * 16 + g + h * 8;
                int row = row0 + lrow;
                float h0 = 0.f, h1 = 0.f;
                if (row < N_NODES) {
                    float* dst = H + (size_t)row * 128 + col;
                    float2 old = *(float2*)dst;
                    h0 = old.x + c[m][n][2 * h] + b3s[col];
                    h1 = old.y + c[m][n][2 * h + 1] + b3s[col + 1];
                    *(float2*)dst = make_float2(h0, h1);
                }
                if (has_c1) As[lrow * W2S + wd] = pack_bf(h0, h1);
            }
        }
    if (!has_c1) return;
    for (int i = tid; i < 128 * 64; i += 256)
        Ws[(i >> 6) * W2S + (i & 63)] = pkWc1[i];
    __syncthreads();

    // ---- phase C: hnew @ Wc1 -> Xf ----
    #pragma unroll
    for (int m = 0; m < 4; m++)
        #pragma unroll
        for (int n = 0; n < 2; n++)
            #pragma unroll
            for (int q = 0; q < 4; q++) c[m][n][q] = 0.f;
    #pragma unroll
    for (int kk = 0; kk < 8; kk++) {
        int wb = kk * 8 + t4;
        u32 b[2][2];
        #pragma unroll
        for (int n = 0; n < 2; n++) {
            int col = n0 + n * 8 + g;
            b[n][0] = Ws[col * W2S + wb];
            b[n][1] = Ws[col * W2S + wb + 4];
        }
        #pragma unroll
        for (int m = 0; m < 4; m++) {
            int r = m * 16 + g;
            u32 a0 = As[r * W2S + wb],     a1 = As[(r + 8) * W2S + wb];
            u32 a2 = As[r * W2S + wb + 4], a3 = As[(r + 8) * W2S + wb + 4];
            #pragma unroll
            for (int n = 0; n < 2; n++)
                mma16(c[m][n][0], c[m][n][1], c[m][n][2], c[m][n][3], a0, a1, a2, a3, b[n][0], b[n][1]);
        }
    }
    #pragma unroll
    for (int m = 0; m < 4; m++)
        #pragma unroll
        for (int n = 0; n < 2; n++) {
            int col = n0 + n * 8 + 2 * t4;
            #pragma unroll
            for (int h = 0; h < 2; h++) {
                int row = row0 + m * 16 + g + h * 8;
                if (row < N_NODES)
                    *(float2*)(Xf + (size_t)row * 128 + col) =
                        make_float2(c[m][n][2 * h], c[m][n][2 * h + 1]);
            }
        }
}

// ---------------- fused edge kernel (bf16 MMA, depth-1 pipelined epilogue) ----
__global__ __launch_bounds__(256, 2) void edge_mm(const u32* __restrict__ pkW1,
                                                  const float* __restrict__ b1,
                                                  const u32* __restrict__ pkW2,
                                                  const float* __restrict__ b2) {
    extern __shared__ u32 sm[];
    u32* As1 = sm;                      // [128 edges][W1S]
    u32* Bs1 = As1 + 128 * W1S;         // [128 n][W1S]
    u32* As2 = Bs1 + 128 * W1S;         // [128 edges][W2S]
    u32* Bs2 = As2 + 128 * W2S;         // [128 n][W2S]
    float* sC  = (float*)(Bs2 + 128 * W2S);
    int*   sS  = (int*)(sC + 128);
    int*   sD  = sS + 128;
    float* b1s = (float*)(sD + 128);
    float* b2s = b1s + 128;

    int tid = threadIdx.x, lane = tid & 31, w = tid >> 5;
    int g = lane >> 2, t4 = lane & 3;
    int wr = w >> 2, wc = w & 3;
    int n0 = wc * 32;
    int r0w = wr * 64;

    for (int i = tid; i < 128 * 32; i += 256)
        Bs1[(i >> 5) * W1S + (i & 31)] = pkW1[i];
    for (int i = tid; i < 128 * 64; i += 256)
        Bs2[(i >> 6) * W2S + (i & 63)] = pkW2[i];
    if (tid < 128) { b1s[tid] = b1[tid]; b2s[tid] = b2[tid]; }
    __syncthreads();

    const float L2E = 1.4426950408889634f;
    const float step = 5.0f / 49.0f;
    const float c2 = (-0.5f / (step * step)) * L2E;

    for (int tile = blockIdx.x; tile < E_EDGES / 128; tile += gridDim.x) {
        if (tid < 128) {
            int e = tile * 128 + tid;
            sC[tid] = g_C[e]; sS[tid] = g_src[e]; sD[tid] = g_dst[e];
        }
        {   // gaussians: 2 threads per edge, 16 bf16x2 words each
            int el = tid >> 1, half = tid & 1;
            float d = g_d[tile * 128 + el];
            float sr = d * 0.2f;
            float l2env = -1e30f;
            if (sr < 1.f) l2env = (1.f - __frcp_rn(1.f - sr * sr)) * L2E;
            #pragma unroll
            for (int j = 0; j < 16; j++) {
                int k = 2 * (half * 16 + j);
                float t0 = d - step * (float)k;
                float t1 = d - step * (float)(k + 1);
                float v0 = (k < NG) ? ex2f(c2 * t0 * t0 + l2env) : 0.f;
                float v1 = (k + 1 < NG) ? ex2f(c2 * t1 * t1 + l2env) : 0.f;
                As1[el * W1S + half * 16 + j] = pack_bf(v0, v1);
            }
        }
        __syncthreads();

        float c[4][4][4];
        #pragma unroll
        for (int m = 0; m < 4; m++)
            #pragma unroll
            for (int n = 0; n < 4; n++)
                #pragma unroll
                for (int q = 0; q < 4; q++) c[m][n][q] = 0.f;

        // phase 1: [128x64] @ w1
        #pragma unroll
        for (int kk = 0; kk < 4; kk++) {
            int wb = kk * 8 + t4;
            u32 b[4][2];
            #pragma unroll
            for (int n = 0; n < 4; n++) {
                int col = n0 + n * 8 + g;
                b[n][0] = Bs1[col * W1S + wb];
                b[n][1] = Bs1[col * W1S + wb + 4];
            }
            #pragma unroll
            for (int m = 0; m < 4; m++) {
                int r = r0w + m * 16 + g;
                u32 a0 = As1[r * W1S + wb],     a1 = As1[(r + 8) * W1S + wb];
                u32 a2 = As1[r * W1S + wb + 4], a3 = As1[(r + 8) * W1S + wb + 4];
                #pragma unroll
                for (int n = 0; n < 4; n++)
                    mma16(c[m][n][0], c[m][n][1], c[m][n][2], c[m][n][3], a0, a1, a2, a3, b[n][0], b[n][1]);
            }
        }
        // t = ssp(D1+b1) -> As2
        #pragma unroll
        for (int m = 0; m < 4; m++)
            #pragma unroll
            for (int n = 0; n < 4; n++) {
                int col = n0 + n * 8 + 2 * t4;
                int wd = wc * 16 + n * 4 + t4;
                #pragma unroll
                for (int h = 0; h < 2; h++) {
                    int row = r0w + m * 16 + g + h * 8;
                    As2[row * W2S + wd] = pack_bf(ssp_fast(c[m][n][2 * h] + b1s[col]),
                                                  ssp_fast(c[m][n][2 * h + 1] + b1s[col + 1]));
                }
            }
        __syncthreads();

        // phase 2: [128x128] @ w2
        #pragma unroll
        for (int m = 0; m < 4; m++)
            #pragma unroll
            for (int n = 0; n < 4; n++)
                #pragma unroll
                for (int q = 0; q < 4; q++) c[m][n][q] = 0.f;
        #pragma unroll
        for (int kk = 0; kk < 8; kk++) {
            int wb = kk * 8 + t4;
            u32 b[4][2];
            #pragma unroll
            for (int n = 0; n < 4; n++) {
                int col = n0 + n * 8 + g;
                b[n][0] = Bs2[col * W2S + wb];
                b[n][1] = Bs2[col * W2S + wb + 4];
            }
            #pragma unroll
            for (int m = 0; m < 4; m++) {
                int r = r0w + m * 16 + g;
                u32 a0 = As2[r * W2S + wb],     a1 = As2[(r + 8) * W2S + wb];
                u32 a2 = As2[r * W2S + wb + 4], a3 = As2[(r + 8) * W2S + wb + 4];
                #pragma unroll
                for (int n = 0; n < 4; n++)
                    mma16(c[m][n][0], c[m][n][1], c[m][n][2], c[m][n][3], a0, a1, a2, a3, b[n][0], b[n][1]);
            }
        }

        // register epilogue, depth-1 pipelined gathers (8 extra regs only)
        {
            float2 cur[4], nxt[4];
            {
                const float* xfp = g_xf + (size_t)sS[r0w + g] * 128;
                #pragma unroll
                for (int n = 0; n < 4; n++)
                    cur[n] = *(const float2*)(xfp + n0 + n * 8 + 2 * t4);
            }
            #pragma unroll
            for (int p = 0; p < 8; p++) {
                int m = p >> 1, h = p & 1;
                int el = r0w + m * 16 + g + h * 8;
                if (p < 7) {
                    int pn = p + 1;
                    int eln = r0w + (pn >> 1) * 16 + g + (pn & 1) * 8;
                    const float* xfp = g_xf + (size_t)sS[eln] * 128;
                    #pragma unroll
                    for (int n = 0; n < 4; n++)
                        nxt[n] = *(const float2*)(xfp + n0 + n * 8 + 2 * t4);
                }
                float Cv = sC[el];
                float* agp = g_agg + (size_t)sD[el] * 128;
                #pragma unroll
                for (int n = 0; n < 4; n++) {
                    int col = n0 + n * 8 + 2 * t4;
                    float v0 = (c[m][n][2 * h]     + b2s[col])     * Cv * cur[n].x;
                    float v1 = (c[m][n][2 * h + 1] + b2s[col + 1]) * Cv * cur[n].y;
                    red2(agp + col, v0, v1);
                }
                #pragma unroll
                for (int n = 0; n < 4; n++) cur[n] = nxt[n];
            }
        }
        __syncthreads();
    }
}

// ---------------- readout ----------------------------------------------------
__global__ __launch_bounds__(128) void readout_kernel(const float* __restrict__ w1,
                                                      const float* __restrict__ b1,
                                                      const float* __restrict__ w2,
                                                      const float* __restrict__ b2v,
                                                      const int* __restrict__ batch,
                                                      float* __restrict__ out) {
    __shared__ float w1s[128 * 64];
    __shared__ float w2s2[64];
    __shared__ float hs[2][128];
    __shared__ float red[2][64];
    int tid = threadIdx.x;
    for (int i = tid; i < 128 * 64; i += 128) w1s[i] = w1[i];
    if (tid < 64) w2s2[tid] = w2[tid];
    __syncthreads();
    int half = tid >> 6, c = tid & 63;
    float b1r = b1[c], b2r = b2v[0];
    const int npairs = N_NODES / 2;
    for (int pair = blockIdx.x; pair < npairs; pair += gridDim.x) {
        for (int i = tid; i < 256; i += 128)
            hs[i >> 7][i & 127] = g_h[(size_t)(pair * 2 + (i >> 7)) * 128 + (i & 127)];
        __syncthreads();
        float acc = b1r;
        #pragma unroll 4
        for (int k = 0; k < 128; k++) acc += hs[half][k] * w1s[k * 64 + c];
        red[half][c] = sspf(acc) * w2s2[c];
        __syncthreads();
        if (c < 32) {
            float v = red[half][c] + red[half][c + 32];
            #pragma unroll
            for (int off = 16; off >= 1; off >>= 1) v += __shfl_down_sync(0xffffffffu, v, off);
            if (c == 0) atomicAdd(&out[batch[pair * 2 + half]], v + b2r);
        }
        __syncthreads();
    }
}

// ---------------- launch ------------------------------------------------------
extern "C" void kernel_launch(void* const* d_in, const int* in_sizes, int n_in,
                              void* d_out, int out_size) {
    const int*   z       = (const int*)d_in[0];
    const float* pos     = (const float*)d_in[1];
    const int*   ei      = (const int*)d_in[2];
    const int*   batch   = (const int*)d_in[3];
    const float* emb     = (const float*)d_in[4];
    const float* mlp_w1  = (const float*)d_in[5];
    const float* mlp_b1  = (const float*)d_in[6];
    const float* mlp_w2  = (const float*)d_in[7];
    const float* mlp_b2  = (const float*)d_in[8];
    const float* conv1_w = (const float*)d_in[9];
    const float* conv2_w = (const float*)d_in[10];
    const float* conv2_b = (const float*)d_in[11];
    const float* lin_w   = (const float*)d_in[12];
    const float* lin_b   = (const float*)d_in[13];
    const float* out1_w  = (const float*)d_in[14];
    const float* out1_b  = (const float*)d_in[15];
    const float* out2_w  = (const float*)d_in[16];
    const float* out2_b  = (const float*)d_in[17];

    const int CONV1_SMEM = (64 + 128) * W2S * 4;
    const int GEMM2_SMEM = ((64 + 128) * W2S + 256) * 4;
    const int EDGE_SMEM  = (2 * 128 * W1S + 2 * 128 * W2S + 640) * 4;
    cudaFuncSetAttribute(mm_conv1, cudaFuncAttributeMaxDynamicSharedMemorySize, CONV1_SMEM);
    cudaFuncSetAttribute(gemm2f, cudaFuncAttributeMaxDynamicSharedMemorySize, GEMM2_SMEM);
    cudaFuncSetAttribute(edge_mm, cudaFuncAttributeMaxDynamicSharedMemorySize, EDGE_SMEM);

    float *hP, *xfP, *aggP;
    u32 *pc1, *pc2, *pl, *pw1, *pw2;
    cudaGetSymbolAddress((void**)&hP, g_h);
    cudaGetSymbolAddress((void**)&xfP, g_xf);
    cudaGetSymbolAddress((void**)&aggP, g_agg);
    cudaGetSymbolAddress((void**)&pc1, pk_c1);
    cudaGetSymbolAddress((void**)&pc2, pk_c2);
    cudaGetSymbolAddress((void**)&pl, pk_l);
    cudaGetSymbolAddress((void**)&pw1, pk_w1);
    cudaGetSymbolAddress((void**)&pw2, pk_w2);

    detect_kernel<<<1, 32>>>(ei);
    pack_kernel<<<(3 * 128 * 64 + 255) / 256, 256>>>(conv1_w, conv2_w, lin_w, mlp_w1, mlp_w2);
    prep_kernel<<<(E_EDGES + 255) / 256, 256>>>(ei, pos);
    embed_kernel<<<(N_NODES * 32 + 255) / 256, 256>>>(z, emb);
    cudaMemsetAsync(aggP, 0, (size_t)N_NODES * 128 * sizeof(float));  // layer-0 only

    const int gg = (N_NODES + 63) / 64;   // 782
    mm_conv1<<<gg, 256, CONV1_SMEM>>>(hP, pc1, xfP);
    for (int l = 0; l < 3; l++) {
        edge_mm<<<296, 256, EDGE_SMEM>>>(pw1 + (size_t)l * 4096,
                                         mlp_b1 + (size_t)l * 128,
                                         pw2 + (size_t)l * 8192,
                                         mlp_b2 + (size_t)l * 128);
        gemm2f<<<gg, 256, GEMM2_SMEM>>>(aggP, pc2 + (size_t)l * 8192,
                                        conv2_b + (size_t)l * 128,
                                        pl + (size_t)l * 8192,
                                        lin_b + (size_t)l * 128,
                                        pc1 + (size_t)(l < 2 ? l + 1 : 0) * 8192,
                                        hP, xfP, l < 2 ? 1 : 0);
    }

    cudaMemsetAsync(d_out, 0, NGRAPHS * sizeof(float));
    readout_kernel<<<1024, 128>>>(out1_w, out1_b, out2_w, out2_b, batch, (float*)d_out);
}

// round 14
// speedup vs baseline: 1.3493x; 1.3493x over previous
#include <cuda_runtime.h>
#include <math.h>

#define N_NODES 50000
#define E_EDGES 640000
#define NG 50
#define NGRAPHS 64

typedef unsigned int u32;

// ---------------- scratch ----------------------------------------------------
__device__ __align__(16) float g_d[E_EDGES];
__device__ __align__(16) float g_C[E_EDGES];
__device__ __align__(16) int   g_src[E_EDGES];
__device__ __align__(16) int   g_dst[E_EDGES];
__device__ __align__(16) float g_h[(size_t)N_NODES * 128];
__device__ __align__(16) float g_xf[(size_t)N_NODES * 128];
__device__ __align__(16) float g_agg[(size_t)N_NODES * 128];
__device__ int g_is64;

// pre-packed bf16x2 weights: layout [n][k-pair]
__device__ __align__(16) u32 pk_c1[3 * 128 * 64];
__device__ __align__(16) u32 pk_c2[3 * 128 * 64];
__device__ __align__(16) u32 pk_l [3 * 128 * 64];
__device__ __align__(16) u32 pk_w1[3 * 128 * 32];
__device__ __align__(16) u32 pk_w2[3 * 128 * 64];

// ---------------- helpers -----------------------------------------------------
__device__ __forceinline__ u32 pack_bf(float lo, float hi) {
    u32 r; asm("cvt.rn.bf16x2.f32 %0,%1,%2;" : "=r"(r) : "f"(hi), "f"(lo)); return r;
}
__device__ __forceinline__ void mma16(float& c0, float& c1, float& c2, float& c3,
                                      u32 a0, u32 a1, u32 a2, u32 a3, u32 b0, u32 b1) {
    asm("mma.sync.aligned.m16n8k16.row.col.f32.bf16.bf16.f32 "
        "{%0,%1,%2,%3},{%4,%5,%6,%7},{%8,%9},{%0,%1,%2,%3};"
        : "+f"(c0), "+f"(c1), "+f"(c2), "+f"(c3)
        : "r"(a0), "r"(a1), "r"(a2), "r"(a3), "r"(b0), "r"(b1));
}
__device__ __forceinline__ float ex2f(float x) { float r; asm("ex2.approx.ftz.f32 %0,%1;" : "=f"(r) : "f"(x)); return r; }
__device__ __forceinline__ float lg2f_(float x) { float r; asm("lg2.approx.ftz.f32 %0,%1;" : "=f"(r) : "f"(x)); return r; }
__device__ __forceinline__ float ssp_fast(float x) {
    float e = ex2f(x * 1.4426950408889634f);
    return 0.6931471805599453f * (lg2f_(1.0f + e) - 1.0f);
}
__device__ __forceinline__ float sspf(float x) {
    float ax = fabsf(x);
    float sp = log1pf(__expf(-ax));
    return (x > 0.f ? x + sp : sp) - 0.6931471805599453f;
}
__device__ __forceinline__ void red2(float* p, float v0, float v1) {
    asm volatile("red.global.add.v2.f32 [%0], {%1,%2};" :: "l"(p), "f"(v0), "f"(v1) : "memory");
}

// ---------------- small kernels ----------------------------------------------
__global__ void detect_kernel(const int* __restrict__ ei) {
    if (threadIdx.x == 0 && blockIdx.x == 0) {
        int acc = ei[1] | ei[3] | ei[5] | ei[7] | ei[9] | ei[11] | ei[13] | ei[15];
        g_is64 = (acc == 0) ? 1 : 0;
    }
}
__global__ void prep_kernel(const int* __restrict__ ei, const float* __restrict__ pos) {
    int e = blockIdx.x * blockDim.x + threadIdx.x;
    if (e >= E_EDGES) return;
    int s, t;
    if (g_is64) { const long long* q = (const long long*)ei; s = (int)q[e]; t = (int)q[E_EDGES + e]; }
    else { s = ei[e]; t = ei[E_EDGES + e]; }
    float dx = pos[t * 3 + 0] - pos[s * 3 + 0];
    float dy = pos[t * 3 + 1] - pos[s * 3 + 1];
    float dz = pos[t * 3 + 2] - pos[s * 3 + 2];
    float d = sqrtf(dx * dx + dy * dy + dz * dz);
    g_src[e] = s; g_dst[e] = t; g_d[e] = d;
    g_C[e] = 0.5f * (cosf(d * 0.62831853071795864f) + 1.0f);
}
__global__ void embed_kernel(const int* __restrict__ z, const float* __restrict__ emb) {
    int i = blockIdx.x * blockDim.x + threadIdx.x;
    if (i >= N_NODES * 32) return;
    int n = i >> 5, c4 = (i & 31) * 4;
    *(float4*)&g_h[(size_t)n * 128 + c4] = *(const float4*)&emb[z[n] * 128 + c4];
}

// ---------------- weight pre-pack ---------------------------------------------
__global__ void pack_kernel(const float* __restrict__ c1, const float* __restrict__ c2,
                            const float* __restrict__ lw, const float* __restrict__ w1,
                            const float* __restrict__ w2) {
    int i = blockIdx.x * blockDim.x + threadIdx.x;
    if (i < 3 * 128 * 64) {
        int l = i >> 13, n = (i >> 6) & 127, wd = i & 63;
        int base = l * 16384, k0 = 2 * wd;
        pk_c1[i] = pack_bf(c1[base + k0 * 128 + n], c1[base + (k0 + 1) * 128 + n]);
        pk_c2[i] = pack_bf(c2[base + k0 * 128 + n], c2[base + (k0 + 1) * 128 + n]);
        pk_l[i]  = pack_bf(lw[base + k0 * 128 + n], lw[base + (k0 + 1) * 128 + n]);
        pk_w2[i] = pack_bf(w2[base + k0 * 128 + n], w2[base + (k0 + 1) * 128 + n]);
    }
    if (i < 3 * 128 * 32) {
        int l = i >> 12, n = (i >> 5) & 127, wd = i & 31;
        int base = l * NG * 128, k0 = 2 * wd;
        float v0 = (k0 < NG) ? w1[base + k0 * 128 + n] : 0.f;
        float v1 = (k0 + 1 < NG) ? w1[base + (k0 + 1) * 128 + n] : 0.f;
        pk_w1[l * 4096 + n * 32 + wd] = pack_bf(v0, v1);
    }
}

#define W1S 36
#define W2S 68

// ---------------- conv1 (layer 0 only) ----------------------------------------
__global__ __launch_bounds__(256, 3) void mm_conv1(const float* __restrict__ A,
                                                   const u32* __restrict__ pkW,
                                                   float* __restrict__ Cout) {
    extern __shared__ u32 sm[];
    u32* As = sm;
    u32* Ws = sm + 64 * W2S;
    int tid = threadIdx.x, lane = tid & 31, w = tid >> 5;
    int row0 = blockIdx.x * 64;

    for (int i = tid; i < 64 * 64; i += 256) {
        int r = i >> 6, wd = i & 63;
        int row = row0 + r;
        float2 v = make_float2(0.f, 0.f);
        if (row < N_NODES) v = *(const float2*)(A + (size_t)row * 128 + 2 * wd);
        As[r * W2S + wd] = pack_bf(v.x, v.y);
    }
    for (int i = tid; i < 128 * 64; i += 256)
        Ws[(i >> 6) * W2S + (i & 63)] = pkW[i];
    __syncthreads();

    int g = lane >> 2, t4 = lane & 3;
    int n0 = w * 16;
    float c[4][2][4];
    #pragma unroll
    for (int m = 0; m < 4; m++)
        #pragma unroll
        for (int n = 0; n < 2; n++)
            #pragma unroll
            for (int q = 0; q < 4; q++) c[m][n][q] = 0.f;

    #pragma unroll
    for (int kk = 0; kk < 8; kk++) {
        int wb = kk * 8 + t4;
        u32 b[2][2];
        #pragma unroll
        for (int n = 0; n < 2; n++) {
            int col = n0 + n * 8 + g;
            b[n][0] = Ws[col * W2S + wb];
            b[n][1] = Ws[col * W2S + wb + 4];
        }
        #pragma unroll
        for (int m = 0; m < 4; m++) {
            int r = m * 16 + g;
            u32 a0 = As[r * W2S + wb],     a1 = As[(r + 8) * W2S + wb];
            u32 a2 = As[r * W2S + wb + 4], a3 = As[(r + 8) * W2S + wb + 4];
            #pragma unroll
            for (int n = 0; n < 2; n++)
                mma16(c[m][n][0], c[m][n][1], c[m][n][2], c[m][n][3], a0, a1, a2, a3, b[n][0], b[n][1]);
        }
    }
    #pragma unroll
    for (int m = 0; m < 4; m++)
        #pragma unroll
        for (int n = 0; n < 2; n++) {
            int col = n0 + n * 8 + 2 * t4;
            #pragma unroll
            for (int h = 0; h < 2; h++) {
                int row = row0 + m * 16 + g + h * 8;
                if (row < N_NODES)
                    *(float2*)(Cout + (size_t)row * 128 + col) =
                        make_float2(c[m][n][2 * h], c[m][n][2 * h + 1]);
            }
        }
}

// ---------------- fused conv2 + lin (+ next conv1); zeroes agg ---------------
__global__ __launch_bounds__(256, 3) void gemm2f(float* __restrict__ Agg,
                                                 const u32* __restrict__ pkW2,
                                                 const float* __restrict__ b2,
                                                 const u32* __restrict__ pkW3,
                                                 const float* __restrict__ b3,
                                                 const u32* __restrict__ pkWc1,
                                                 float* __restrict__ H,
                                                 float* __restrict__ Xf,
                                                 int has_c1) {
    extern __shared__ u32 sm[];
    u32* As = sm;
    u32* Ws = sm + 64 * W2S;
    float* b2s = (float*)(Ws + 128 * W2S);
    float* b3s = b2s + 128;
    int tid = threadIdx.x, lane = tid & 31, w = tid >> 5;
    int row0 = blockIdx.x * 64;
    int g = lane >> 2, t4 = lane & 3;
    int n0 = w * 16;

    for (int i = tid; i < 64 * 64; i += 256) {
        int r = i >> 6, wd = i & 63;
        int row = row0 + r;
        float2 v = make_float2(0.f, 0.f);
        if (row < N_NODES) {
            float* p = Agg + (size_t)row * 128 + 2 * wd;
            v = *(float2*)p;
            *(float2*)p = make_float2(0.f, 0.f);
        }
        As[r * W2S + wd] = pack_bf(v.x, v.y);
    }
    for (int i = tid; i < 128 * 64; i += 256)
        Ws[(i >> 6) * W2S + (i & 63)] = pkW2[i];
    if (tid < 128) { b2s[tid] = b2[tid]; b3s[tid] = b3[tid]; }
    __syncthreads();

    float c[4][2][4];
    #pragma unroll
    for (int m = 0; m < 4; m++)
        #pragma unroll
        for (int n = 0; n < 2; n++)
            #pragma unroll
            for (int q = 0; q < 4; q++) c[m][n][q] = 0.f;

    // ---- phase A: agg @ W2 ----
    #pragma unroll
    for (int kk = 0; kk < 8; kk++) {
        int wb = kk * 8 + t4;
        u32 b[2][2];
        #pragma unroll
        for (int n = 0; n < 2; n++) {
            int col = n0 + n * 8 + g;
            b[n][0] = Ws[col * W2S + wb];
            b[n][1] = Ws[col * W2S + wb + 4];
        }
        #pragma unroll
        for (int m = 0; m < 4; m++) {
            int r = m * 16 + g;
            u32 a0 = As[r * W2S + wb],     a1 = As[(r + 8) * W2S + wb];
            u32 a2 = As[r * W2S + wb + 4], a3 = As[(r + 8) * W2S + wb + 4];
            #pragma unroll
            for (int n = 0; n < 2; n++)
                mma16(c[m][n][0], c[m][n][1], c[m][n][2], c[m][n][3], a0, a1, a2, a3, b[n][0], b[n][1]);
        }
    }
    __syncthreads();

    // t = ssp(c + b2) -> As ; Ws <- W3
    #pragma unroll
    for (int m = 0; m < 4; m++)
        #pragma unroll
        for (int n = 0; n < 2; n++) {
            int col = n0 + n * 8 + 2 * t4;
            int wd = w * 8 + n * 4 + t4;
            #pragma unroll
            for (int h = 0; h < 2; h++) {
                int row = m * 16 + g + h * 8;
                As[row * W2S + wd] = pack_bf(ssp_fast(c[m][n][2 * h] + b2s[col]),
                                             ssp_fast(c[m][n][2 * h + 1] + b2s[col + 1]));
            }
        }
    for (int i = tid; i < 128 * 64; i += 256)
        Ws[(i >> 6) * W2S + (i & 63)] = pkW3[i];
    __syncthreads();

    // ---- phase B: t @ W3 ----
    #pragma unroll
    for (int m = 0; m < 4; m++)
        #pragma unroll
        for (int n = 0; n < 2; n++)
            #pragma unroll
            for (int q = 0; q < 4; q++) c[m][n][q] = 0.f;
    #pragma unroll
    for (int kk = 0; kk < 8; kk++) {
        int wb = kk * 8 + t4;
        u32 b[2][2];
        #pragma unroll
        for (int n = 0; n < 2; n++) {
            int col = n0 + n * 8 + g;
            b[n][0] = Ws[col * W2S + wb];
            b[n][1] = Ws[col * W2S + wb + 4];
        }
        #pragma unroll
        for (int m = 0; m < 4; m++) {
            int r = m * 16 + g;
            u32 a0 = As[r * W2S + wb],     a1 = As[(r + 8) * W2S + wb];
            u32 a2 = As[r * W2S + wb + 4], a3 = As[(r + 8) * W2S + wb + 4];
            #pragma unroll
            for (int n = 0; n < 2; n++)
                mma16(c[m][n][0], c[m][n][1], c[m][n][2], c[m][n][3], a0, a1, a2, a3, b[n][0], b[n][1]);
        }
    }
    __syncthreads();

    // hnew = h + c + b3 -> H (and As for phase C) ; Ws <- Wc1
    #pragma unroll
    for (int m = 0; m < 4; m++)
        #pragma unroll
        for (int n = 0; n < 2; n++) {
            int col = n0 + n * 8 + 2 * t4;
            int wd = w * 8 + n * 4 + t4;
            #pragma unroll
            for (int h = 0; h < 2; h++) {
                int lrow = m * 16 + g + h * 8;
                int row = row0 + lrow;
                float h0 = 0.f, h1 = 0.f;
                if (row < N_NODES) {
                    float* dst = H + (size_t)row * 128 + col;
                    float2 old = *(float2*)dst;
                    h0 = old.x + c[m][n][2 * h] + b3s[col];
                    h1 = old.y + c[m][n][2 * h + 1] + b3s[col + 1];
                    *(float2*)dst = make_float2(h0, h1);
                }
                if (has_c1) As[lrow * W2S + wd] = pack_bf(h0, h1);
            }
        }
    if (!has_c1) return;
    for (int i = tid; i < 128 * 64; i += 256)
        Ws[(i >> 6) * W2S + (i & 63)] = pkWc1[i];
    __syncthreads();

    // ---- phase C: hnew @ Wc1 -> Xf ----
    #pragma unroll
    for (int m = 0; m < 4; m++)
        #pragma unroll
        for (int n = 0; n < 2; n++)
            #pragma unroll
            for (int q = 0; q < 4; q++) c[m][n][q] = 0.f;
    #pragma unroll
    for (int kk = 0; kk < 8; kk++) {
        int wb = kk * 8 + t4;
        u32 b[2][2];
        #pragma unroll
        for (int n = 0; n < 2; n++) {
            int col = n0 + n * 8 + g;
            b[n][0] = Ws[col * W2S + wb];
            b[n][1] = Ws[col * W2S + wb + 4];
        }
        #pragma unroll
        for (int m = 0; m < 4; m++) {
            int r = m * 16 + g;
            u32 a0 = As[r * W2S + wb],     a1 = As[(r + 8) * W2S + wb];
            u32 a2 = As[r * W2S + wb + 4], a3 = As[(r + 8) * W2S + wb + 4];
            #pragma unroll
            for (int n = 0; n < 2; n++)
                mma16(c[m][n][0], c[m][n][1], c[m][n][2], c[m][n][3], a0, a1, a2, a3, b[n][0], b[n][1]);
        }
    }
    #pragma unroll
    for (int m = 0; m < 4; m++)
        #pragma unroll
        for (int n = 0; n < 2; n++) {
            int col = n0 + n * 8 + 2 * t4;
            #pragma unroll
            for (int h = 0; h < 2; h++) {
                int row = row0 + m * 16 + g + h * 8;
                if (row < N_NODES)
                    *(float2*)(Xf + (size_t)row * 128 + col) =
                        make_float2(c[m][n][2 * h], c[m][n][2 * h + 1]);
            }
        }
}

// ---------------- fused edge kernel (bf16 MMA, R10 interleaved epilogue) ------
__global__ __launch_bounds__(256, 2) void edge_mm(const u32* __restrict__ pkW1,
                                                  const float* __restrict__ b1,
                                                  const u32* __restrict__ pkW2,
                                                  const float* __restrict__ b2) {
    extern __shared__ u32 sm[];
    u32* As1 = sm;                      // [128 edges][W1S]
    u32* Bs1 = As1 + 128 * W1S;         // [128 n][W1S]
    u32* As2 = Bs1 + 128 * W1S;         // [128 edges][W2S]
    u32* Bs2 = As2 + 128 * W2S;         // [128 n][W2S]
    float* sC  = (float*)(Bs2 + 128 * W2S);
    int*   sS  = (int*)(sC + 128);
    int*   sD  = sS + 128;
    float* b1s = (float*)(sD + 128);
    float* b2s = b1s + 128;

    int tid = threadIdx.x, lane = tid & 31, w = tid >> 5;
    int g = lane >> 2, t4 = lane & 3;
    int wr = w >> 2, wc = w & 3;
    int n0 = wc * 32;
    int r0w = wr * 64;

    for (int i = tid; i < 128 * 32; i += 256)
        Bs1[(i >> 5) * W1S + (i & 31)] = pkW1[i];
    for (int i = tid; i < 128 * 64; i += 256)
        Bs2[(i >> 6) * W2S + (i & 63)] = pkW2[i];
    if (tid < 128) { b1s[tid] = b1[tid]; b2s[tid] = b2[tid]; }
    __syncthreads();

    const float L2E = 1.4426950408889634f;
    const float step = 5.0f / 49.0f;
    const float c2 = (-0.5f / (step * step)) * L2E;

    for (int tile = blockIdx.x; tile < E_EDGES / 128; tile += gridDim.x) {
        if (tid < 128) {
            int e = tile * 128 + tid;
            sC[tid] = g_C[e]; sS[tid] = g_src[e]; sD[tid] = g_dst[e];
        }
        {   // gaussians: 2 threads per edge, 16 bf16x2 words each
            int el = tid >> 1, half = tid & 1;
            float d = g_d[tile * 128 + el];
            float sr = d * 0.2f;
            float l2env = -1e30f;
            if (sr < 1.f) l2env = (1.f - __frcp_rn(1.f - sr * sr)) * L2E;
            #pragma unroll
            for (int j = 0; j < 16; j++) {
                int k = 2 * (half * 16 + j);
                float t0 = d - step * (float)k;
                float t1 = d - step * (float)(k + 1);
                float v0 = (k < NG) ? ex2f(c2 * t0 * t0 + l2env) : 0.f;
                float v1 = (k + 1 < NG) ? ex2f(c2 * t1 * t1 + l2env) : 0.f;
                As1[el * W1S + half * 16 + j] = pack_bf(v0, v1);
            }
        }
        __syncthreads();

        float c[4][4][4];
        #pragma unroll
        for (int m = 0; m < 4; m++)
            #pragma unroll
            for (int n = 0; n < 4; n++)
                #pragma unroll
                for (int q = 0; q < 4; q++) c[m][n][q] = 0.f;

        // phase 1: [128x64] @ w1
        #pragma unroll
        for (int kk = 0; kk < 4; kk++) {
            int wb = kk * 8 + t4;
            u32 b[4][2];
            #pragma unroll
            for (int n = 0; n < 4; n++) {
                int col = n0 + n * 8 + g;
                b[n][0] = Bs1[col * W1S + wb];
                b[n][1] = Bs1[col * W1S + wb + 4];
            }
            #pragma unroll
            for (int m = 0; m < 4; m++) {
                int r = r0w + m * 16 + g;
                u32 a0 = As1[r * W1S + wb],     a1 = As1[(r + 8) * W1S + wb];
                u32 a2 = As1[r * W1S + wb + 4], a3 = As1[(r + 8) * W1S + wb + 4];
                #pragma unroll
                for (int n = 0; n < 4; n++)
                    mma16(c[m][n][0], c[m][n][1], c[m][n][2], c[m][n][3], a0, a1, a2, a3, b[n][0], b[n][1]);
            }
        }
        // t = ssp(D1+b1) -> As2
        #pragma unroll
        for (int m = 0; m < 4; m++)
            #pragma unroll
            for (int n = 0; n < 4; n++) {
                int col = n0 + n * 8 + 2 * t4;
                int wd = wc * 16 + n * 4 + t4;
                #pragma unroll
                for (int h = 0; h < 2; h++) {
                    int row = r0w + m * 16 + g + h * 8;
                    As2[row * W2S + wd] = pack_bf(ssp_fast(c[m][n][2 * h] + b1s[col]),
                                                  ssp_fast(c[m][n][2 * h + 1] + b1s[col + 1]));
                }
            }
        __syncthreads();

        // phase 2: [128x128] @ w2
        #pragma unroll
        for (int m = 0; m < 4; m++)
            #pragma unroll
            for (int n = 0; n < 4; n++)
                #pragma unroll
                for (int q = 0; q < 4; q++) c[m][n][q] = 0.f;
        #pragma unroll
        for (int kk = 0; kk < 8; kk++) {
            int wb = kk * 8 + t4;
            u32 b[4][2];
            #pragma unroll
            for (int n = 0; n < 4; n++) {
                int col = n0 + n * 8 + g;
                b[n][0] = Bs2[col * W2S + wb];
                b[n][1] = Bs2[col * W2S + wb + 4];
            }
            #pragma unroll
            for (int m = 0; m < 4; m++) {
                int r = r0w + m * 16 + g;
                u32 a0 = As2[r * W2S + wb],     a1 = As2[(r + 8) * W2S + wb];
                u32 a2 = As2[r * W2S + wb + 4], a3 = As2[(r + 8) * W2S + wb + 4];
                #pragma unroll
                for (int n = 0; n < 4; n++)
                    mma16(c[m][n][0], c[m][n][1], c[m][n][2], c[m][n][3], a0, a1, a2, a3, b[n][0], b[n][1]);
            }
        }

        // register epilogue (R10 form): msg = (D2+b2)*C*xf[src] -> red into agg[dst]
        #pragma unroll
        for (int m = 0; m < 4; m++) {
            #pragma unroll
            for (int h = 0; h < 2; h++) {
                int el = r0w + m * 16 + g + h * 8;
                float Cv = sC[el];
                const float* xfp = g_xf + (size_t)sS[el] * 128;
                float* agp = g_agg + (size_t)sD[el] * 128;
                #pragma unroll
                for (int n = 0; n < 4; n++) {
                    int col = n0 + n * 8 + 2 * t4;
                    float2 x = *(const float2*)(xfp + col);
                    float v0 = (c[m][n][2 * h]     + b2s[col])     * Cv * x.x;
                    float v1 = (c[m][n][2 * h + 1] + b2s[col + 1]) * Cv * x.y;
                    red2(agp + col, v0, v1);
                }
            }
        }
        __syncthreads();
    }
}

// ---------------- readout ----------------------------------------------------
__global__ __launch_bounds__(128) void readout_kernel(const float* __restrict__ w1,
                                                      const float* __restrict__ b1,
                                                      const float* __restrict__ w2,
                                                      const float* __restrict__ b2v,
                                                      const int* __restrict__ batch,
                                                      float* __restrict__ out) {
    __shared__ float w1s[128 * 64];
    __shared__ float w2s2[64];
    __shared__ float hs[2][128];
    __shared__ float red[2][64];
    int tid = threadIdx.x;
    for (int i = tid; i < 128 * 64; i += 128) w1s[i] = w1[i];
    if (tid < 64) w2s2[tid] = w2[tid];
    __syncthreads();
    int half = tid >> 6, c = tid & 63;
    float b1r = b1[c], b2r = b2v[0];
    const int npairs = N_NODES / 2;
    for (int pair = blockIdx.x; pair < npairs; pair += gridDim.x) {
        for (int i = tid; i < 256; i += 128)
            hs[i >> 7][i & 127] = g_h[(size_t)(pair * 2 + (i >> 7)) * 128 + (i & 127)];
        __syncthreads();
        float acc = b1r;
        #pragma unroll 4
        for (int k = 0; k < 128; k++) acc += hs[half][k] * w1s[k * 64 + c];
        red[half][c] = sspf(acc) * w2s2[c];
        __syncthreads();
        if (c < 32) {
            float v = red[half][c] + red[half][c + 32];
            #pragma unroll
            for (int off = 16; off >= 1; off >>= 1) v += __shfl_down_sync(0xffffffffu, v, off);
            if (c == 0) atomicAdd(&out[batch[pair * 2 + half]], v + b2r);
        }
        __syncthreads();
    }
}

// ---------------- launch ------------------------------------------------------
extern "C" void kernel_launch(void* const* d_in, const int* in_sizes, int n_in,
                              void* d_out, int out_size) {
    const int*   z       = (const int*)d_in[0];
    const float* pos     = (const float*)d_in[1];
    const int*   ei      = (const int*)d_in[2];
    const int*   batch   = (const int*)d_in[3];
    const float* emb     = (const float*)d_in[4];
    const float* mlp_w1  = (const float*)d_in[5];
    const float* mlp_b1  = (const float*)d_in[6];
    const float* mlp_w2  = (const float*)d_in[7];
    const float* mlp_b2  = (const float*)d_in[8];
    const float* conv1_w = (const float*)d_in[9];
    const float* conv2_w = (const float*)d_in[10];
    const float* conv2_b = (const float*)d_in[11];
    const float* lin_w   = (const float*)d_in[12];
    const float* lin_b   = (const float*)d_in[13];
    const float* out1_w  = (const float*)d_in[14];
    const float* out1_b  = (const float*)d_in[15];
    const float* out2_w  = (const float*)d_in[16];
    const float* out2_b  = (const float*)d_in[17];

    const int CONV1_SMEM = (64 + 128) * W2S * 4;
    const int GEMM2_SMEM = ((64 + 128) * W2S + 256) * 4;
    const int EDGE_SMEM  = (2 * 128 * W1S + 2 * 128 * W2S + 640) * 4;
    cudaFuncSetAttribute(mm_conv1, cudaFuncAttributeMaxDynamicSharedMemorySize, CONV1_SMEM);
    cudaFuncSetAttribute(gemm2f, cudaFuncAttributeMaxDynamicSharedMemorySize, GEMM2_SMEM);
    cudaFuncSetAttribute(edge_mm, cudaFuncAttributeMaxDynamicSharedMemorySize, EDGE_SMEM);

    float *hP, *xfP, *aggP;
    u32 *pc1, *pc2, *pl, *pw1, *pw2;
    cudaGetSymbolAddress((void**)&hP, g_h);
    cudaGetSymbolAddress((void**)&xfP, g_xf);
    cudaGetSymbolAddress((void**)&aggP, g_agg);
    cudaGetSymbolAddress((void**)&pc1, pk_c1);
    cudaGetSymbolAddress((void**)&pc2, pk_c2);
    cudaGetSymbolAddress((void**)&pl, pk_l);
    cudaGetSymbolAddress((void**)&pw1, pk_w1);
    cudaGetSymbolAddress((void**)&pw2, pk_w2);

    detect_kernel<<<1, 32>>>(ei);
    pack_kernel<<<(3 * 128 * 64 + 255) / 256, 256>>>(conv1_w, conv2_w, lin_w, mlp_w1, mlp_w2);
    prep_kernel<<<(E_EDGES + 255) / 256, 256>>>(ei, pos);
    embed_kernel<<<(N_NODES * 32 + 255) / 256, 256>>>(z, emb);
    cudaMemsetAsync(aggP, 0, (size_t)N_NODES * 128 * sizeof(float));  // layer-0 only

    const int gg = (N_NODES + 63) / 64;   // 782
    mm_conv1<<<gg, 256, CONV1_SMEM>>>(hP, pc1, xfP);
    for (int l = 0; l < 3; l++) {
        edge_mm<<<296, 256, EDGE_SMEM>>>(pw1 + (size_t)l * 4096,
                                         mlp_b1 + (size_t)l * 128,
                                         pw2 + (size_t)l * 8192,
                                         mlp_b2 + (size_t)l * 128);
        gemm2f<<<gg, 256, GEMM2_SMEM>>>(aggP, pc2 + (size_t)l * 8192,
                                        conv2_b + (size_t)l * 128,
                                        pl + (size_t)l * 8192,
                                        lin_b + (size_t)l * 128,
                                        pc1 + (size_t)(l < 2 ? l + 1 : 0) * 8192,
                                        hP, xfP, l < 2 ? 1 : 0);
    }

    cudaMemsetAsync(d_out, 0, NGRAPHS * sizeof(float));
    readout_kernel<<<1024, 128>>>(out1_w, out1_b, out2_w, out2_b, batch, (float*)d_out);
}

// round 15
// speedup vs baseline: 1.5584x; 1.1550x over previous
#include <cuda_runtime.h>
#include <math.h>

#define N_NODES 50000
#define E_EDGES 640000
#define NG 50
#define NGRAPHS 64

typedef unsigned int u32;

// ---------------- scratch ----------------------------------------------------
__device__ __align__(16) float g_d[E_EDGES];
__device__ __align__(16) float g_C[E_EDGES];
__device__ __align__(16) int   g_src[E_EDGES];
__device__ __align__(16) int   g_dst[E_EDGES];
__device__ __align__(16) float g_h[(size_t)N_NODES * 128];
__device__ __align__(16) float g_xf[(size_t)N_NODES * 128];
__device__ __align__(16) float g_agg[(size_t)N_NODES * 128];
__device__ int g_is64;

// pre-packed bf16x2 weights: layout [n][k-pair]
__device__ __align__(16) u32 pk_c1[3 * 128 * 64];
__device__ __align__(16) u32 pk_c2[3 * 128 * 64];
__device__ __align__(16) u32 pk_l [3 * 128 * 64];
__device__ __align__(16) u32 pk_w1[3 * 128 * 32];
__device__ __align__(16) u32 pk_w2[3 * 128 * 64];

// ---------------- helpers -----------------------------------------------------
__device__ __forceinline__ u32 pack_bf(float lo, float hi) {
    u32 r; asm("cvt.rn.bf16x2.f32 %0,%1,%2;" : "=r"(r) : "f"(hi), "f"(lo)); return r;
}
__device__ __forceinline__ void mma16(float& c0, float& c1, float& c2, float& c3,
                                      u32 a0, u32 a1, u32 a2, u32 a3, u32 b0, u32 b1) {
    asm("mma.sync.aligned.m16n8k16.row.col.f32.bf16.bf16.f32 "
        "{%0,%1,%2,%3},{%4,%5,%6,%7},{%8,%9},{%0,%1,%2,%3};"
        : "+f"(c0), "+f"(c1), "+f"(c2), "+f"(c3)
        : "r"(a0), "r"(a1), "r"(a2), "r"(a3), "r"(b0), "r"(b1));
}
__device__ __forceinline__ float ex2f(float x) { float r; asm("ex2.approx.ftz.f32 %0,%1;" : "=f"(r) : "f"(x)); return r; }
__device__ __forceinline__ float lg2f_(float x) { float r; asm("lg2.approx.ftz.f32 %0,%1;" : "=f"(r) : "f"(x)); return r; }
__device__ __forceinline__ float ssp_fast(float x) {
    float e = ex2f(x * 1.4426950408889634f);
    return 0.6931471805599453f * (lg2f_(1.0f + e) - 1.0f);
}
__device__ __forceinline__ float sspf(float x) {
    float ax = fabsf(x);
    float sp = log1pf(__expf(-ax));
    return (x > 0.f ? x + sp : sp) - 0.6931471805599453f;
}
__device__ __forceinline__ void red2(float* p, float v0, float v1) {
    asm volatile("red.global.add.v2.f32 [%0], {%1,%2};" :: "l"(p), "f"(v0), "f"(v1) : "memory");
}

// ---------------- small kernels ----------------------------------------------
__global__ void detect_kernel(const int* __restrict__ ei) {
    if (threadIdx.x == 0 && blockIdx.x == 0) {
        int acc = ei[1] | ei[3] | ei[5] | ei[7] | ei[9] | ei[11] | ei[13] | ei[15];
        g_is64 = (acc == 0) ? 1 : 0;
    }
}
__global__ void prep_kernel(const int* __restrict__ ei, const float* __restrict__ pos) {
    int e = blockIdx.x * blockDim.x + threadIdx.x;
    if (e >= E_EDGES) return;
    int s, t;
    if (g_is64) { const long long* q = (const long long*)ei; s = (int)q[e]; t = (int)q[E_EDGES + e]; }
    else { s = ei[e]; t = ei[E_EDGES + e]; }
    float dx = pos[t * 3 + 0] - pos[s * 3 + 0];
    float dy = pos[t * 3 + 1] - pos[s * 3 + 1];
    float dz = pos[t * 3 + 2] - pos[s * 3 + 2];
    float d = sqrtf(dx * dx + dy * dy + dz * dz);
    g_src[e] = s; g_dst[e] = t; g_d[e] = d;
    g_C[e] = 0.5f * (cosf(d * 0.62831853071795864f) + 1.0f);
}
__global__ void embed_kernel(const int* __restrict__ z, const float* __restrict__ emb) {
    int i = blockIdx.x * blockDim.x + threadIdx.x;
    if (i >= N_NODES * 32) return;
    int n = i >> 5, c4 = (i & 31) * 4;
    *(float4*)&g_h[(size_t)n * 128 + c4] = *(const float4*)&emb[z[n] * 128 + c4];
}

// ---------------- weight pre-pack ---------------------------------------------
__global__ void pack_kernel(const float* __restrict__ c1, const float* __restrict__ c2,
                            const float* __restrict__ lw, const float* __restrict__ w1,
                            const float* __restrict__ w2) {
    int i = blockIdx.x * blockDim.x + threadIdx.x;
    if (i < 3 * 128 * 64) {
        int l = i >> 13, n = (i >> 6) & 127, wd = i & 63;
        int base = l * 16384, k0 = 2 * wd;
        pk_c1[i] = pack_bf(c1[base + k0 * 128 + n], c1[base + (k0 + 1) * 128 + n]);
        pk_c2[i] = pack_bf(c2[base + k0 * 128 + n], c2[base + (k0 + 1) * 128 + n]);
        pk_l[i]  = pack_bf(lw[base + k0 * 128 + n], lw[base + (k0 + 1) * 128 + n]);
        pk_w2[i] = pack_bf(w2[base + k0 * 128 + n], w2[base + (k0 + 1) * 128 + n]);
    }
    if (i < 3 * 128 * 32) {
        int l = i >> 12, n = (i >> 5) & 127, wd = i & 31;
        int base = l * NG * 128, k0 = 2 * wd;
        float v0 = (k0 < NG) ? w1[base + k0 * 128 + n] : 0.f;
        float v1 = (k0 + 1 < NG) ? w1[base + (k0 + 1) * 128 + n] : 0.f;
        pk_w1[l * 4096 + n * 32 + wd] = pack_bf(v0, v1);
    }
}

#define W1S 36
#define W2S 68

// ---------------- conv1 (layer 0 only) ----------------------------------------
__global__ __launch_bounds__(256, 3) void mm_conv1(const float* __restrict__ A,
                                                   const u32* __restrict__ pkW,
                                                   float* __restrict__ Cout) {
    extern __shared__ u32 sm[];
    u32* As = sm;
    u32* Ws = sm + 64 * W2S;
    int tid = threadIdx.x, lane = tid & 31, w = tid >> 5;
    int row0 = blockIdx.x * 64;

    for (int i = tid; i < 64 * 64; i += 256) {
        int r = i >> 6, wd = i & 63;
        int row = row0 + r;
        float2 v = make_float2(0.f, 0.f);
        if (row < N_NODES) v = *(const float2*)(A + (size_t)row * 128 + 2 * wd);
        As[r * W2S + wd] = pack_bf(v.x, v.y);
    }
    for (int i = tid; i < 128 * 64; i += 256)
        Ws[(i >> 6) * W2S + (i & 63)] = pkW[i];
    __syncthreads();

    int g = lane >> 2, t4 = lane & 3;
    int n0 = w * 16;
    float c[4][2][4];
    #pragma unroll
    for (int m = 0; m < 4; m++)
        #pragma unroll
        for (int n = 0; n < 2; n++)
            #pragma unroll
            for (int q = 0; q < 4; q++) c[m][n][q] = 0.f;

    #pragma unroll
    for (int kk = 0; kk < 8; kk++) {
        int wb = kk * 8 + t4;
        u32 b[2][2];
        #pragma unroll
        for (int n = 0; n < 2; n++) {
            int col = n0 + n * 8 + g;
            b[n][0] = Ws[col * W2S + wb];
            b[n][1] = Ws[col * W2S + wb + 4];
        }
        #pragma unroll
        for (int m = 0; m < 4; m++) {
            int r = m * 16 + g;
            u32 a0 = As[r * W2S + wb],     a1 = As[(r + 8) * W2S + wb];
            u32 a2 = As[r * W2S + wb + 4], a3 = As[(r + 8) * W2S + wb + 4];
            #pragma unroll
            for (int n = 0; n < 2; n++)
                mma16(c[m][n][0], c[m][n][1], c[m][n][2], c[m][n][3], a0, a1, a2, a3, b[n][0], b[n][1]);
        }
    }
    #pragma unroll
    for (int m = 0; m < 4; m++)
        #pragma unroll
        for (int n = 0; n < 2; n++) {
            int col = n0 + n * 8 + 2 * t4;
            #pragma unroll
            for (int h = 0; h < 2; h++) {
                int row = row0 + m * 16 + g + h * 8;
                if (row < N_NODES)
                    *(float2*)(Cout + (size_t)row * 128 + col) =
                        make_float2(c[m][n][2 * h], c[m][n][2 * h + 1]);
            }
        }
}

// ---------------- fused conv2 + lin (+ next conv1): 3-phase bf16 --------------
__global__ __launch_bounds__(256, 3) void gemm2f(const float* __restrict__ Agg,
                                                 const u32* __restrict__ pkW2,
                                                 const float* __restrict__ b2,
                                                 const u32* __restrict__ pkW3,
                                                 const float* __restrict__ b3,
                                                 const u32* __restrict__ pkWc1,
                                                 float* __restrict__ H,
                                                 float* __restrict__ Xf,
                                                 int has_c1) {
    extern __shared__ u32 sm[];
    u32* As = sm;
    u32* Ws = sm + 64 * W2S;
    float* b2s = (float*)(Ws + 128 * W2S);
    float* b3s = b2s + 128;
    int tid = threadIdx.x, lane = tid & 31, w = tid >> 5;
    int row0 = blockIdx.x * 64;
    int g = lane >> 2, t4 = lane & 3;
    int n0 = w * 16;

    for (int i = tid; i < 64 * 64; i += 256) {
        int r = i >> 6, wd = i & 63;
        int row = row0 + r;
        float2 v = make_float2(0.f, 0.f);
        if (row < N_NODES) v = *(const float2*)(Agg + (size_t)row * 128 + 2 * wd);
        As[r * W2S + wd] = pack_bf(v.x, v.y);
    }
    for (int i = tid; i < 128 * 64; i += 256)
        Ws[(i >> 6) * W2S + (i & 63)] = pkW2[i];
    if (tid < 128) { b2s[tid] = b2[tid]; b3s[tid] = b3[tid]; }
    __syncthreads();

    float c[4][2][4];
    #pragma unroll
    for (int m = 0; m < 4; m++)
        #pragma unroll
        for (int n = 0; n < 2; n++)
            #pragma unroll
            for (int q = 0; q < 4; q++) c[m][n][q] = 0.f;

    // ---- phase A: agg @ W2 ----
    #pragma unroll
    for (int kk = 0; kk < 8; kk++) {
        int wb = kk * 8 + t4;
        u32 b[2][2];
        #pragma unroll
        for (int n = 0; n < 2; n++) {
            int col = n0 + n * 8 + g;
            b[n][0] = Ws[col * W2S + wb];
            b[n][1] = Ws[col * W2S + wb + 4];
        }
        #pragma unroll
        for (int m = 0; m < 4; m++) {
            int r = m * 16 + g;
            u32 a0 = As[r * W2S + wb],     a1 = As[(r + 8) * W2S + wb];
            u32 a2 = As[r * W2S + wb + 4], a3 = As[(r + 8) * W2S + wb + 4];
            #pragma unroll
            for (int n = 0; n < 2; n++)
                mma16(c[m][n][0], c[m][n][1], c[m][n][2], c[m][n][3], a0, a1, a2, a3, b[n][0], b[n][1]);
        }
    }
    __syncthreads();

    // t = ssp(c + b2) -> As ; Ws <- W3
    #pragma unroll
    for (int m = 0; m < 4; m++)
        #pragma unroll
        for (int n = 0; n < 2; n++) {
            int col = n0 + n * 8 + 2 * t4;
            int wd = w * 8 + n * 4 + t4;
            #pragma unroll
            for (int h = 0; h < 2; h++) {
                int row = m * 16 + g + h * 8;
                As[row * W2S + wd] = pack_bf(ssp_fast(c[m][n][2 * h] + b2s[col]),
                                             ssp_fast(c[m][n][2 * h + 1] + b2s[col + 1]));
            }
        }
    for (int i = tid; i < 128 * 64; i += 256)
        Ws[(i >> 6) * W2S + (i & 63)] = pkW3[i];
    __syncthreads();

    // ---- phase B: t @ W3 ----
    #pragma unroll
    for (int m = 0; m < 4; m++)
        #pragma unroll
        for (int n = 0; n < 2; n++)
            #pragma unroll
            for (int q = 0; q < 4; q++) c[m][n][q] = 0.f;
    #pragma unroll
    for (int kk = 0; kk < 8; kk++) {
        int wb = kk * 8 + t4;
        u32 b[2][2];
        #pragma unroll
        for (int n = 0; n < 2; n++) {
            int col = n0 + n * 8 + g;
            b[n][0] = Ws[col * W2S + wb];
            b[n][1] = Ws[col * W2S + wb + 4];
        }
        #pragma unroll
        for (int m = 0; m < 4; m++) {
            int r = m * 16 + g;
            u32 a0 = As[r * W2S + wb],     a1 = As[(r + 8) * W2S + wb];
            u32 a2 = As[r * W2S + wb + 4], a3 = As[(r + 8) * W2S + wb + 4];
            #pragma unroll
            for (int n = 0; n < 2; n++)
                mma16(c[m][n][0], c[m][n][1], c[m][n][2], c[m][n][3], a0, a1, a2, a3, b[n][0], b[n][1]);
        }
    }
    __syncthreads();

    // hnew = h + c + b3 -> H (and As for phase C) ; Ws <- Wc1
    #pragma unroll
    for (int m = 0; m < 4; m++)
        #pragma unroll
        for (int n = 0; n < 2; n++) {
            int col = n0 + n * 8 + 2 * t4;
            int wd = w * 8 + n * 4 + t4;
            #pragma unroll
            for (int h = 0; h < 2; h++) {
                int lrow = m * 16 + g + h * 8;
                int row = row0 + lrow;
                float h0 = 0.f, h1 = 0.f;
                if (row < N_NODES) {
                    float* dst = H + (size_t)row * 128 + col;
                    float2 old = *(float2*)dst;
                    h0 = old.x + c[m][n][2 * h] + b3s[col];
                    h1 = old.y + c[m][n][2 * h + 1] + b3s[col + 1];
                    *(float2*)dst = make_float2(h0, h1);
                }
                if (has_c1) As[lrow * W2S + wd] = pack_bf(h0, h1);
            }
        }
    if (!has_c1) return;
    for (int i = tid; i < 128 * 64; i += 256)
        Ws[(i >> 6) * W2S + (i & 63)] = pkWc1[i];
    __syncthreads();

    // ---- phase C: hnew @ Wc1 -> Xf ----
    #pragma unroll
    for (int m = 0; m < 4; m++)
        #pragma unroll
        for (int n = 0; n < 2; n++)
            #pragma unroll
            for (int q = 0; q < 4; q++) c[m][n][q] = 0.f;
    #pragma unroll
    for (int kk = 0; kk < 8; kk++) {
        int wb = kk * 8 + t4;
        u32 b[2][2];
        #pragma unroll
        for (int n = 0; n < 2; n++) {
            int col = n0 + n * 8 + g;
            b[n][0] = Ws[col * W2S + wb];
            b[n][1] = Ws[col * W2S + wb + 4];
        }
        #pragma unroll
        for (int m = 0; m < 4; m++) {
            int r = m * 16 + g;
            u32 a0 = As[r * W2S + wb],     a1 = As[(r + 8) * W2S + wb];
            u32 a2 = As[r * W2S + wb + 4], a3 = As[(r + 8) * W2S + wb + 4];
            #pragma unroll
            for (int n = 0; n < 2; n++)
                mma16(c[m][n][0], c[m][n][1], c[m][n][2], c[m][n][3], a0, a1, a2, a3, b[n][0], b[n][1]);
        }
    }
    #pragma unroll
    for (int m = 0; m < 4; m++)
        #pragma unroll
        for (int n = 0; n < 2; n++) {
            int col = n0 + n * 8 + 2 * t4;
            #pragma unroll
            for (int h = 0; h < 2; h++) {
                int row = row0 + m * 16 + g + h * 8;
                if (row < N_NODES)
                    *(float2*)(Xf + (size_t)row * 128 + col) =
                        make_float2(c[m][n][2 * h], c[m][n][2 * h + 1]);
            }
        }
}

// ---------------- fused edge kernel (bf16 MMA, R10 interleaved epilogue) ------
__global__ __launch_bounds__(256, 2) void edge_mm(const u32* __restrict__ pkW1,
                                                  const float* __restrict__ b1,
                                                  const u32* __restrict__ pkW2,
                                                  const float* __restrict__ b2) {
    extern __shared__ u32 sm[];
    u32* As1 = sm;                      // [128 edges][W1S]
    u32* Bs1 = As1 + 128 * W1S;         // [128 n][W1S]
    u32* As2 = Bs1 + 128 * W1S;         // [128 edges][W2S]
    u32* Bs2 = As2 + 128 * W2S;         // [128 n][W2S]
    float* sC  = (float*)(Bs2 + 128 * W2S);
    int*   sS  = (int*)(sC + 128);
    int*   sD  = sS + 128;
    float* b1s = (float*)(sD + 128);
    float* b2s = b1s + 128;

    int tid = threadIdx.x, lane = tid & 31, w = tid >> 5;
    int g = lane >> 2, t4 = lane & 3;
    int wr = w >> 2, wc = w & 3;
    int n0 = wc * 32;
    int r0w = wr * 64;

    for (int i = tid; i < 128 * 32; i += 256)
        Bs1[(i >> 5) * W1S + (i & 31)] = pkW1[i];
    for (int i = tid; i < 128 * 64; i += 256)
        Bs2[(i >> 6) * W2S + (i & 63)] = pkW2[i];
    if (tid < 128) { b1s[tid] = b1[tid]; b2s[tid] = b2[tid]; }
    __syncthreads();

    const float L2E = 1.4426950408889634f;
    const float step = 5.0f / 49.0f;
    const float c2 = (-0.5f / (step * step)) * L2E;

    for (int tile = blockIdx.x; tile < E_EDGES / 128; tile += gridDim.x) {
        if (tid < 128) {
            int e = tile * 128 + tid;
            sC[tid] = g_C[e]; sS[tid] = g_src[e]; sD[tid] = g_dst[e];
        }
        {   // gaussians: 2 threads per edge, 16 bf16x2 words each
            int el = tid >> 1, half = tid & 1;
            float d = g_d[tile * 128 + el];
            float sr = d * 0.2f;
            float l2env = -1e30f;
            if (sr < 1.f) l2env = (1.f - __frcp_rn(1.f - sr * sr)) * L2E;
            #pragma unroll
            for (int j = 0; j < 16; j++) {
                int k = 2 * (half * 16 + j);
                float t0 = d - step * (float)k;
                float t1 = d - step * (float)(k + 1);
                float v0 = (k < NG) ? ex2f(c2 * t0 * t0 + l2env) : 0.f;
                float v1 = (k + 1 < NG) ? ex2f(c2 * t1 * t1 + l2env) : 0.f;
                As1[el * W1S + half * 16 + j] = pack_bf(v0, v1);
            }
        }
        __syncthreads();

        float c[4][4][4];
        #pragma unroll
        for (int m = 0; m < 4; m++)
            #pragma unroll
            for (int n = 0; n < 4; n++)
                #pragma unroll
                for (int q = 0; q < 4; q++) c[m][n][q] = 0.f;

        // phase 1: [128x64] @ w1
        #pragma unroll
        for (int kk = 0; kk < 4; kk++) {
            int wb = kk * 8 + t4;
            u32 b[4][2];
            #pragma unroll
            for (int n = 0; n < 4; n++) {
                int col = n0 + n * 8 + g;
                b[n][0] = Bs1[col * W1S + wb];
                b[n][1] = Bs1[col * W1S + wb + 4];
            }
            #pragma unroll
            for (int m = 0; m < 4; m++) {
                int r = r0w + m * 16 + g;
                u32 a0 = As1[r * W1S + wb],     a1 = As1[(r + 8) * W1S + wb];
                u32 a2 = As1[r * W1S + wb + 4], a3 = As1[(r + 8) * W1S + wb + 4];
                #pragma unroll
                for (int n = 0; n < 4; n++)
                    mma16(c[m][n][0], c[m][n][1], c[m][n][2], c[m][n][3], a0, a1, a2, a3, b[n][0], b[n][1]);
            }
        }
        // t = ssp(D1+b1) -> As2
        #pragma unroll
        for (int m = 0; m < 4; m++)
            #pragma unroll
            for (int n = 0; n < 4; n++) {
                int col = n0 + n * 8 + 2 * t4;
                int wd = wc * 16 + n * 4 + t4;
                #pragma unroll
                for (int h = 0; h < 2; h++) {
                    int row = r0w + m * 16 + g + h * 8;
                    As2[row * W2S + wd] = pack_bf(ssp_fast(c[m][n][2 * h] + b1s[col]),
                                                  ssp_fast(c[m][n][2 * h + 1] + b1s[col + 1]));
                }
            }
        __syncthreads();

        // phase 2: [128x128] @ w2
        #pragma unroll
        for (int m = 0; m < 4; m++)
            #pragma unroll
            for (int n = 0; n < 4; n++)
                #pragma unroll
                for (int q = 0; q < 4; q++) c[m][n][q] = 0.f;
        #pragma unroll
        for (int kk = 0; kk < 8; kk++) {
            int wb = kk * 8 + t4;
            u32 b[4][2];
            #pragma unroll
            for (int n = 0; n < 4; n++) {
                int col = n0 + n * 8 + g;
                b[n][0] = Bs2[col * W2S + wb];
                b[n][1] = Bs2[col * W2S + wb + 4];
            }
            #pragma unroll
            for (int m = 0; m < 4; m++) {
                int r = r0w + m * 16 + g;
                u32 a0 = As2[r * W2S + wb],     a1 = As2[(r + 8) * W2S + wb];
                u32 a2 = As2[r * W2S + wb + 4], a3 = As2[(r + 8) * W2S + wb + 4];
                #pragma unroll
                for (int n = 0; n < 4; n++)
                    mma16(c[m][n][0], c[m][n][1], c[m][n][2], c[m][n][3], a0, a1, a2, a3, b[n][0], b[n][1]);
            }
        }

        // register epilogue (R10 form): msg = (D2+b2)*C*xf[src] -> red into agg[dst]
        #pragma unroll
        for (int m = 0; m < 4; m++) {
            #pragma unroll
            for (int h = 0; h < 2; h++) {
                int el = r0w + m * 16 + g + h * 8;
                float Cv = sC[el];
                const float* xfp = g_xf + (size_t)sS[el] * 128;
                float* agp = g_agg + (size_t)sD[el] * 128;
                #pragma unroll
                for (int n = 0; n < 4; n++) {
                    int col = n0 + n * 8 + 2 * t4;
                    float2 x = *(const float2*)(xfp + col);
                    float v0 = (c[m][n][2 * h]     + b2s[col])     * Cv * x.x;
                    float v1 = (c[m][n][2 * h + 1] + b2s[col + 1]) * Cv * x.y;
                    red2(agp + col, v0, v1);
                }
            }
        }
        __syncthreads();
    }
}

// ---------------- readout ----------------------------------------------------
__global__ __launch_bounds__(128) void readout_kernel(const float* __restrict__ w1,
                                                      const float* __restrict__ b1,
                                                      const float* __restrict__ w2,
                                                      const float* __restrict__ b2v,
                                                      const int* __restrict__ batch,
                                                      float* __restrict__ out) {
    __shared__ float w1s[128 * 64];
    __shared__ float w2s2[64];
    __shared__ float hs[2][128];
    __shared__ float red[2][64];
    int tid = threadIdx.x;
    for (int i = tid; i < 128 * 64; i += 128) w1s[i] = w1[i];
    if (tid < 64) w2s2[tid] = w2[tid];
    __syncthreads();
    int half = tid >> 6, c = tid & 63;
    float b1r = b1[c], b2r = b2v[0];
    const int npairs = N_NODES / 2;
    for (int pair = blockIdx.x; pair < npairs; pair += gridDim.x) {
        for (int i = tid; i < 256; i += 128)
            hs[i >> 7][i & 127] = g_h[(size_t)(pair * 2 + (i >> 7)) * 128 + (i & 127)];
        __syncthreads();
        float acc = b1r;
        #pragma unroll 4
        for (int k = 0; k < 128; k++) acc += hs[half][k] * w1s[k * 64 + c];
        red[half][c] = sspf(acc) * w2s2[c];
        __syncthreads();
        if (c < 32) {
            float v = red[half][c] + red[half][c + 32];
            #pragma unroll
            for (int off = 16; off >= 1; off >>= 1) v += __shfl_down_sync(0xffffffffu, v, off);
            if (c == 0) atomicAdd(&out[batch[pair * 2 + half]], v + b2r);
        }
        __syncthreads();
    }
}

// ---------------- launch ------------------------------------------------------
extern "C" void kernel_launch(void* const* d_in, const int* in_sizes, int n_in,
                              void* d_out, int out_size) {
    const int*   z       = (const int*)d_in[0];
    const float* pos     = (const float*)d_in[1];
    const int*   ei      = (const int*)d_in[2];
    const int*   batch   = (const int*)d_in[3];
    const float* emb     = (const float*)d_in[4];
    const float* mlp_w1  = (const float*)d_in[5];
    const float* mlp_b1  = (const float*)d_in[6];
    const float* mlp_w2  = (const float*)d_in[7];
    const float* mlp_b2  = (const float*)d_in[8];
    const float* conv1_w = (const float*)d_in[9];
    const float* conv2_w = (const float*)d_in[10];
    const float* conv2_b = (const float*)d_in[11];
    const float* lin_w   = (const float*)d_in[12];
    const float* lin_b   = (const float*)d_in[13];
    const float* out1_w  = (const float*)d_in[14];
    const float* out1_b  = (const float*)d_in[15];
    const float* out2_w  = (const float*)d_in[16];
    const float* out2_b  = (const float*)d_in[17];

    const int CONV1_SMEM = (64 + 128) * W2S * 4;
    const int GEMM2_SMEM = ((64 + 128) * W2S + 256) * 4;
    const int EDGE_SMEM  = (2 * 128 * W1S + 2 * 128 * W2S + 640) * 4;
    cudaFuncSetAttribute(mm_conv1, cudaFuncAttributeMaxDynamicSharedMemorySize, CONV1_SMEM);
    cudaFuncSetAttribute(gemm2f, cudaFuncAttributeMaxDynamicSharedMemorySize, GEMM2_SMEM);
    cudaFuncSetAttribute(edge_mm, cudaFuncAttributeMaxDynamicSharedMemorySize, EDGE_SMEM);

    float *hP, *xfP, *aggP;
    u32 *pc1, *pc2, *pl, *pw1, *pw2;
    cudaGetSymbolAddress((void**)&hP, g_h);
    cudaGetSymbolAddress((void**)&xfP, g_xf);
    cudaGetSymbolAddress((void**)&aggP, g_agg);
    cudaGetSymbolAddress((void**)&pc1, pk_c1);
    cudaGetSymbolAddress((void**)&pc2, pk_c2);
    cudaGetSymbolAddress((void**)&pl, pk_l);
    cudaGetSymbolAddress((void**)&pw1, pk_w1);
    cudaGetSymbolAddress((void**)&pw2, pk_w2);

    detect_kernel<<<1, 32>>>(ei);
    pack_kernel<<<(3 * 128 * 64 + 255) / 256, 256>>>(conv1_w, conv2_w, lin_w, mlp_w1, mlp_w2);
    prep_kernel<<<(E_EDGES + 255) / 256, 256>>>(ei, pos);
    embed_kernel<<<(N_NODES * 32 + 255) / 256, 256>>>(z, emb);

    const int gg = (N_NODES + 63) / 64;   // 782
    mm_conv1<<<gg, 256, CONV1_SMEM>>>(hP, pc1, xfP);   // layer-0 xf
    for (int l = 0; l < 3; l++) {
        cudaMemsetAsync(aggP, 0, (size_t)N_NODES * 128 * sizeof(float));
        edge_mm<<<296, 256, EDGE_SMEM>>>(pw1 + (size_t)l * 4096,
                                         mlp_b1 + (size_t)l * 128,
                                         pw2 + (size_t)l * 8192,
                                         mlp_b2 + (size_t)l * 128);
        gemm2f<<<gg, 256, GEMM2_SMEM>>>(aggP, pc2 + (size_t)l * 8192,
                                        conv2_b + (size_t)l * 128,
                                        pl + (size_t)l * 8192,
                                        lin_b + (size_t)l * 128,
                                        pc1 + (size_t)(l < 2 ? l + 1 : 0) * 8192,
                                        hP, xfP, l < 2 ? 1 : 0);
    }

    cudaMemsetAsync(d_out, 0, NGRAPHS * sizeof(float));
    readout_kernel<<<1024, 128>>>(out1_w, out1_b, out2_w, out2_b, batch, (float*)d_out);
}